// round 2
// baseline (speedup 1.0000x reference)
#include <cuda_runtime.h>
#include <cuda_bf16.h>

// ConvTreeBlock: N=1e6 nodes, C=16, KS=9.
// R2: coalesced smem-staged gather + fma.rn.f32x2 packed math + full fusion.
// Launches: zero_stats -> conv1(+stats1) -> conv2(inline BN1+leaky on gather, +stats2) -> bnact2.

#define NMAX 1000000
#define CMAX 16

__device__ float g_y1[(size_t)NMAX * CMAX];   // raw conv1 output
__device__ float g_stats[64];                 // [0:16]sum1 [16:32]ssq1 [32:48]sum2 [48:64]ssq2

static constexpr float EPS   = 1e-5f;
static constexpr float SLOPE = 0.2f;

// ---- f32x2 helpers (sm_103a packed fp32; ptxas never auto-fuses these) ----
__device__ __forceinline__ unsigned long long pack2(float lo, float hi) {
    unsigned long long r;
    asm("mov.b64 %0, {%1, %2};" : "=l"(r) : "f"(lo), "f"(hi));
    return r;
}
__device__ __forceinline__ unsigned long long dup2(float x) {
    unsigned long long r;
    asm("mov.b64 %0, {%1, %1};" : "=l"(r) : "f"(x));
    return r;
}
__device__ __forceinline__ void fma2(unsigned long long& acc, unsigned long long a, unsigned long long b) {
    asm("fma.rn.f32x2 %0, %1, %2, %0;" : "+l"(acc) : "l"(a), "l"(b));
}
__device__ __forceinline__ void unpack2(unsigned long long v, float& lo, float& hi) {
    asm("mov.b64 {%0, %1}, %2;" : "=f"(lo), "=f"(hi) : "l"(v));
}

__global__ void k_zero_stats()
{
    if (threadIdx.x < 64) g_stats[threadIdx.x] = 0.0f;
}

// Block = 128 threads, 64 nodes.
// Phase A (gather): 4 lanes per 64B row, LDG.128 coalesced-within-row -> STS.128
//   into sx (node stride 148 floats: 16B-aligned, bank-spread). LAYER==2 applies
//   BN1 affine + leaky per element during the gather (a/b from g_stats).
// Phase B (compute): 2 threads/node, 8 outputs each as 4 f32x2 accumulators.
//   Weights from smem as ulonglong2 (LDS.128 -> two packed pairs).
// Epilogue: STG.128 x2 (coalesced) + shuffle-reduced per-channel sum/ssq ->
//   smem atomics -> 32 global atomics per block.
template<int LAYER>
__global__ __launch_bounds__(128)
void k_conv(const float* __restrict__ src,     // data (L1) | g_y1 (L2)
            const int*   __restrict__ ind,
            const float* __restrict__ w,       // [c][o][j] : c*144 + o*9 + j
            const float* __restrict__ bias,    // L1 only
            const float* __restrict__ gamma,   // L2: gamma1
            const float* __restrict__ beta,    // L2: beta1
            float*       __restrict__ dst,     // g_y1 (L1) | d_out (L2)
            int n, int stat_off_in, int stat_off_out)
{
    __shared__ __align__(16) float ws[2304];        // ws[j*256 + c*16 + o]
    __shared__ __align__(16) float sx[64 * 148];    // sx[node*148 + j*16 + c]
    __shared__ float s_ab[32];                      // a[16], b[16] (LAYER 2)
    __shared__ float s_stat[32];                    // sum[16], ssq[16]

    const int tid = threadIdx.x;

    for (int s = tid; s < 2304; s += 128) {
        int o = s & 15, c = (s >> 4) & 15, j = s >> 8;
        ws[s] = w[c * 144 + o * 9 + j];
    }
    if (tid < 32) s_stat[tid] = 0.0f;
    if (LAYER == 2 && tid < 16) {
        float inv  = 1.0f / (float)n;
        float mean = g_stats[stat_off_in + tid] * inv;
        float var  = g_stats[stat_off_in + 16 + tid] * inv - mean * mean;
        float a    = gamma[tid] * rsqrtf(var + EPS);
        s_ab[tid]      = a;
        s_ab[16 + tid] = beta[tid] - a * mean;
    }
    __syncthreads();

    const int node0 = blockIdx.x * 64;

    // ---- Phase A: gather ----
#pragma unroll
    for (int j = 0; j < 9; ++j) {
#pragma unroll
        for (int k = 0; k < 2; ++k) {
            int i   = tid + k * 128;          // 0..255
            int nl  = i >> 2;                 // local node 0..63
            int l4  = i & 3;                  // quarter of the row
            int gn  = node0 + nl;
            int row = (gn < n) ? ind[gn * 9 + j] : 0;
            float4 v = *reinterpret_cast<const float4*>(src + (size_t)row * 16 + l4 * 4);
            if (LAYER == 2) {
                int c = l4 * 4;
                v.x = fmaf(v.x, s_ab[c + 0], s_ab[16 + c + 0]); v.x = fmaxf(v.x, SLOPE * v.x);
                v.y = fmaf(v.y, s_ab[c + 1], s_ab[16 + c + 1]); v.y = fmaxf(v.y, SLOPE * v.y);
                v.z = fmaf(v.z, s_ab[c + 2], s_ab[16 + c + 2]); v.z = fmaxf(v.z, SLOPE * v.z);
                v.w = fmaf(v.w, s_ab[c + 3], s_ab[16 + c + 3]); v.w = fmaxf(v.w, SLOPE * v.w);
            }
            *reinterpret_cast<float4*>(sx + nl * 148 + j * 16 + l4 * 4) = v;
        }
    }
    __syncthreads();

    // ---- Phase B: compute ----
    const int nl = tid >> 1;                   // local node
    const int p  = tid & 1;                    // output half: ch [8p, 8p+8)
    const int gn = node0 + nl;

    unsigned long long acc[4];
#pragma unroll
    for (int k = 0; k < 4; ++k)
        acc[k] = (LAYER == 1) ? pack2(bias[p * 8 + 2 * k], bias[p * 8 + 2 * k + 1])
                              : pack2(0.0f, 0.0f);

    const float* xrow = sx + nl * 148;
#pragma unroll 1                               // keep body ~1.9KB, fits I$ L0
    for (int j = 0; j < 9; ++j) {
        const float* xj = xrow + j * 16;
        const float* wj = ws + j * 256 + p * 8;
#pragma unroll
        for (int cb = 0; cb < 4; ++cb) {
            float4 xv = *reinterpret_cast<const float4*>(xj + cb * 4);
            float xs[4] = {xv.x, xv.y, xv.z, xv.w};
#pragma unroll
            for (int ci = 0; ci < 4; ++ci) {
                int c = cb * 4 + ci;
                unsigned long long xx = dup2(xs[ci]);
                ulonglong2 w01 = *reinterpret_cast<const ulonglong2*>(wj + c * 16);
                ulonglong2 w23 = *reinterpret_cast<const ulonglong2*>(wj + c * 16 + 4);
                fma2(acc[0], xx, w01.x);
                fma2(acc[1], xx, w01.y);
                fma2(acc[2], xx, w23.x);
                fma2(acc[3], xx, w23.y);
            }
        }
    }

    // ---- Epilogue: store + fused stats ----
    float av[8];
#pragma unroll
    for (int k = 0; k < 4; ++k) unpack2(acc[k], av[2 * k], av[2 * k + 1]);

    if (gn < n) {
        float4* o4 = reinterpret_cast<float4*>(dst + (size_t)gn * 16 + p * 8);
        o4[0] = make_float4(av[0], av[1], av[2], av[3]);
        o4[1] = make_float4(av[4], av[5], av[6], av[7]);
    }

    float m = (gn < n) ? 1.0f : 0.0f;
    float sv[8], qv[8];
#pragma unroll
    for (int k = 0; k < 8; ++k) { sv[k] = av[k] * m; qv[k] = av[k] * av[k] * m; }
    // reduce over node lanes (xor 2,4,8,16); p distinction (bit 0) preserved
#pragma unroll
    for (int d = 2; d < 32; d <<= 1) {
#pragma unroll
        for (int k = 0; k < 8; ++k) {
            sv[k] += __shfl_xor_sync(0xFFFFFFFFu, sv[k], d);
            qv[k] += __shfl_xor_sync(0xFFFFFFFFu, qv[k], d);
        }
    }
    if ((tid & 31) < 2) {                      // lane 0 (p=0: ch0..7), lane 1 (p=1: ch8..15)
#pragma unroll
        for (int k = 0; k < 8; ++k) {
            atomicAdd(&s_stat[p * 8 + k],      sv[k]);
            atomicAdd(&s_stat[16 + p * 8 + k], qv[k]);
        }
    }
    __syncthreads();
    if (tid < 32) atomicAdd(&g_stats[stat_off_out + tid], s_stat[tid]);
}

// Final: out = leaky(a2[c]*y2 + b2[c] + data), in place on d_out.
__global__ __launch_bounds__(256)
void k_bnact2(const float* __restrict__ gamma,
              const float* __restrict__ beta,
              const float* __restrict__ res,
              float*       __restrict__ out,
              int n, int off)
{
    __shared__ float sa[16], sb[16];
    if (threadIdx.x < 16) {
        int c = threadIdx.x;
        float inv  = 1.0f / (float)n;
        float mean = g_stats[off + c] * inv;
        float var  = g_stats[off + 16 + c] * inv - mean * mean;
        float a    = gamma[c] * rsqrtf(var + EPS);
        sa[c] = a;
        sb[c] = beta[c] - a * mean;
    }
    __syncthreads();

    int n4 = n * 4;
    int stride = gridDim.x * 256;
    for (int i = blockIdx.x * 256 + threadIdx.x; i < n4; i += stride) {
        float4 v = reinterpret_cast<float4*>(out)[i];
        float4 r = reinterpret_cast<const float4*>(res)[i];
        int c0 = (i & 3) * 4;
        v.x = fmaf(v.x, sa[c0 + 0], sb[c0 + 0]) + r.x;  v.x = fmaxf(v.x, SLOPE * v.x);
        v.y = fmaf(v.y, sa[c0 + 1], sb[c0 + 1]) + r.y;  v.y = fmaxf(v.y, SLOPE * v.y);
        v.z = fmaf(v.z, sa[c0 + 2], sb[c0 + 2]) + r.z;  v.z = fmaxf(v.z, SLOPE * v.z);
        v.w = fmaf(v.w, sa[c0 + 3], sb[c0 + 3]) + r.w;  v.w = fmaxf(v.w, SLOPE * v.w);
        reinterpret_cast<float4*>(out)[i] = v;
    }
}

extern "C" void kernel_launch(void* const* d_in, const int* in_sizes, int n_in,
                              void* d_out, int out_size)
{
    const float* data   = (const float*)d_in[0];
    const int*   ind    = (const int*)  d_in[1];
    const float* w1     = (const float*)d_in[2];
    const float* b1     = (const float*)d_in[3];
    const float* gamma1 = (const float*)d_in[4];
    const float* beta1  = (const float*)d_in[5];
    const float* w2     = (const float*)d_in[6];
    const float* gamma2 = (const float*)d_in[7];
    const float* beta2  = (const float*)d_in[8];
    float*       out    = (float*)d_out;

    int n = in_sizes[0] / 16;
    if (n > NMAX) n = NMAX;

    int conv_blocks = (n + 63) / 64;
    int ew_blocks   = 1184;

    k_zero_stats<<<1, 64>>>();
    k_conv<1><<<conv_blocks, 128>>>(data, ind, w1, b1, nullptr, nullptr, g_y1, n, 0, 0);
    k_conv<2><<<conv_blocks, 128>>>(g_y1, ind, w2, nullptr, gamma1, beta1, out, n, 0, 32);
    k_bnact2<<<ew_blocks, 256>>>(gamma2, beta2, data, out, n, 32);
}